// round 16
// baseline (speedup 1.0000x reference)
#include <cuda_runtime.h>
#include <cuda_fp16.h>
#include <math.h>
#include <stdint.h>

// ---------------- problem constants ----------------
#define N_ANG   256
#define DET_V   256
#define DET_U   384
#define VOL_N   128
#define D_SO    500.0f
#define D_SD    1000.0f
#define CU      191.5f
#define CV      127.5f
#define CC      63.5f
#define VOL_ELEMS (VOL_N*VOL_N*VOL_N)

// exponent re-centering for the fp16 GEMM: h' = h * 2^9 (exact), undone in epilogue
#define HSCALE     512.0f
#define HSCALE_INV (1.0f/512.0f)

// quad buffer geometry (row index = v0 + 30; border rows stay zero: zero-initialized
// __device__ global, never written)
#define QS_U    392
#define QS_ROWS 314
#define QS_ANG  (QS_U*QS_ROWS)
#define QROW_SHIFT 29

// angle split for BP occupancy
#define ASPLIT  8
#define ACHUNK  (N_ANG/ASPLIT)      // 32

// ---------------- device scratch (zero-initialized at module load) ----------------
__device__ uint32_t g_hpdh[2*DET_U];                      // half2 {hi(h'[i]), hi(h'[i-1])}
__device__ uint32_t g_hpdl[2*DET_U];                      // half2 {lo(h'[i]), lo(h'[i-1])}
__device__ float2   g_trig[N_ANG];
__device__ __half   g_filtP[(size_t)N_ANG*DET_V*DET_U];   // filtered proj, plain half rows (50MB)
__device__ uint4    g_filtQ4[(size_t)N_ANG*QS_ANG/2];     // padded bilinear quads (252MB)
__device__ float    g_part[(size_t)ASPLIT*VOL_ELEMS];

// ---------------- kernel 0: h=irfft(ramp)*(pi/N_ANG) (fp64 DFT) + trig + pair tables ----------------
__global__ __launch_bounds__(192) void prep_h_kernel(const float* __restrict__ ramp) {
    __shared__ double swarp[6];
    int n = blockIdx.x;
    int k = threadIdx.x;

    double term;
    if (k == 0) {
        double nyq = (double)ramp[DET_U/2] * (((n & 1) == 0) ? 1.0 : -1.0);
        term = (double)ramp[0] + nyq;
    } else {
        int m = (k * n) % DET_U;
        term = 2.0 * (double)ramp[k] * cos(2.0 * M_PI * (double)m / (double)DET_U);
    }
    #pragma unroll
    for (int off = 16; off > 0; off >>= 1)
        term += __shfl_down_sync(0xffffffffu, term, off);
    if ((k & 31) == 0) swarp[k >> 5] = term;
    __syncthreads();
    if (k == 0) {
        double acc = 0.0;
        #pragma unroll
        for (int w = 0; w < 6; w++) acc += swarp[w];
        float h  = (float)(acc / (double)DET_U * (M_PI / (double)N_ANG));
        float hp = h * HSCALE;
        __half hih = __float2half_rn(hp);
        unsigned short hb = __half_as_ushort(hih);
        float lof = hp - __half2float(hih);
        unsigned short lb = __half_as_ushort(__float2half_rn(lof));

        unsigned short* TH = reinterpret_cast<unsigned short*>(g_hpdh);
        unsigned short* TL = reinterpret_cast<unsigned short*>(g_hpdl);
        // word i: low half = h'[i%384], high half = h'[(i-1)%384]
        int ia = n + 1;
        int ib = (n + 385) % 768;
        TH[2*n] = hb;           TH[2*(n + 384)] = hb;
        TH[2*ia + 1] = hb;      TH[2*ib + 1] = hb;
        TL[2*n] = lb;           TL[2*(n + 384)] = lb;
        TL[2*ia + 1] = lb;      TL[2*ib + 1] = lb;

        if (n < N_ANG) {
            double th = (double)n * (2.0 * M_PI / (double)N_ANG);
            g_trig[n] = make_float2((float)cos(th), (float)sin(th));
        }
    }
}

// ---------------- kernel 1: filter as 3-pass FP16 tensor-core GEMM (circulant B) ----------------
// S planes stored fragment-major: sA[ksg][row][16] with per-group half permutation
// {2t,2t+1,2t+8,2t+9} so each lane's (A0,A2)/(A1,A3) pair is one aligned LDS.64.
#define FROWS 32
#define KSGN  24                      // 384 / 16
#define KSTRIDE 512                   // 32 rows * 16 halves per ksg
#define FILT_SMEM (2*KSGN*KSTRIDE*2 + 2*768*4)   // two half planes (49152B) + tables (6144B)

#define MMA16(acc, A, b0, b1)                                               \
    asm volatile(                                                           \
        "mma.sync.aligned.m16n8k16.row.col.f32.f16.f16.f32 "                \
        "{%0,%1,%2,%3}, {%4,%5,%6,%7}, {%8,%9}, {%0,%1,%2,%3};"             \
        : "+f"((acc)[0]), "+f"((acc)[1]), "+f"((acc)[2]), "+f"((acc)[3])    \
        : "r"((A)[0]), "r"((A)[1]), "r"((A)[2]), "r"((A)[3]),               \
          "r"(b0), "r"(b1));

__global__ __launch_bounds__(512, 2) void filt_gemm_kernel(const float* __restrict__ proj,
                                                           const float* __restrict__ redund) {
    extern __shared__ __half smh[];
    __half*   sHi  = smh;                             // [KSGN][32][16]
    __half*   sLo  = smh + KSGN*KSTRIDE;              // [KSGN][32][16]
    uint32_t* sTbH = reinterpret_cast<uint32_t*>(smh + 2*KSGN*KSTRIDE);   // [768]
    uint32_t* sTbL = sTbH + 768;                                          // [768]

    int tid  = threadIdx.x;
    int b    = blockIdx.x;
    int a    = b >> 3;
    int v0   = (b & 7) << 5;
    int row0 = b << 5;

    const float* prow = proj   + (size_t)row0 * DET_U;
    const float* rrow = redund + (size_t)a    * DET_U;

    // ---- fill S planes (fragment-major permuted), fp16 hi/lo split ----
    for (int i = tid; i < FROWS * DET_U; i += 512) {
        int r = i / DET_U;
        int c = i - r * DET_U;
        float vv = (float)(v0 + r) - CV;
        float uu = (float)c - CU;
        float cw = D_SD * rsqrtf(D_SD*D_SD + vv*vv + uu*uu);
        float val = prow[i] * cw * rrow[c];
        __half hi = __float2half_rn(val);
        __half lo = __float2half_rn(val - __half2float(hi));
        int ksg = c >> 4;
        int kp  = c & 15;
        int pos = (kp & 1) + 2 * ((kp >> 3) & 1) + 4 * ((kp >> 1) & 3);
        int idx = ksg * KSTRIDE + r * 16 + pos;
        sHi[idx] = hi;
        sLo[idx] = lo;
    }
    for (int i = tid; i < 768; i += 512) {
        sTbH[i] = g_hpdh[i];
        sTbL[i] = g_hpdl[i];
    }
    __syncthreads();

    int w    = tid >> 5;
    int lane = tid & 31;
    int gr   = lane >> 2;
    int tig  = lane & 3;
    int n0   = w * 24;

    float acc[2][3][4];
    #pragma unroll
    for (int mt = 0; mt < 2; mt++)
        #pragma unroll
        for (int nt = 0; nt < 3; nt++)
            #pragma unroll
            for (int q = 0; q < 4; q++) acc[mt][nt][q] = 0.f;

    int afr = gr * 16 + 4 * tig;           // in-ksg offset for row gr
    int bC  = n0 + gr - 2 * tig + 384;

    #pragma unroll 4
    for (int ksg = 0; ksg < KSGN; ksg++) {
        int kb = ksg * KSTRIDE + afr;      // row gr
        uint32_t Ah[2][4], Al[2][4];
        #pragma unroll
        for (int mt = 0; mt < 2; mt++) {
            int o0 = kb + mt * (16 * 16);           // rows gr (+16 for mt=1)
            int o1 = o0 + 8 * 16;                   // rows gr+8 (+16)
            uint2 h02 = *reinterpret_cast<const uint2*>(&sHi[o0]);
            uint2 h13 = *reinterpret_cast<const uint2*>(&sHi[o1]);
            uint2 l02 = *reinterpret_cast<const uint2*>(&sLo[o0]);
            uint2 l13 = *reinterpret_cast<const uint2*>(&sLo[o1]);
            Ah[mt][0] = h02.x; Ah[mt][2] = h02.y;
            Ah[mt][1] = h13.x; Ah[mt][3] = h13.y;
            Al[mt][0] = l02.x; Al[mt][2] = l02.y;
            Al[mt][1] = l13.x; Al[mt][3] = l13.y;
        }
        int ks16 = ksg * 16;
        #pragma unroll
        for (int nt = 0; nt < 3; nt++) {
            int i0 = bC + nt * 8 - ks16;
            uint32_t b0h = sTbH[i0];
            uint32_t b1h = sTbH[i0 - 8];
            uint32_t b0l = sTbL[i0];
            uint32_t b1l = sTbL[i0 - 8];
            #pragma unroll
            for (int mt = 0; mt < 2; mt++) {
                MMA16(acc[mt][nt], Ah[mt], b0h, b1h);   // hi*hi
                MMA16(acc[mt][nt], Ah[mt], b0l, b1l);   // hi*lo
                MMA16(acc[mt][nt], Al[mt], b0h, b1h);   // lo*hi
            }
        }
    }

    // ---- epilogue: un-scale (exact /512), stage fp32 results, write plain half rows ----
    __syncthreads();
    float* Sf = reinterpret_cast<float*>(smh);    // [FROWS][388] (49664B <= 55296B)
    #pragma unroll
    for (int mt = 0; mt < 2; mt++) {
        int r = 16 * mt + gr;
        #pragma unroll
        for (int nt = 0; nt < 3; nt++) {
            int col = n0 + nt * 8 + 2 * tig;
            *reinterpret_cast<float2*>(&Sf[r * 388 + col]) =
                make_float2(acc[mt][nt][0] * HSCALE_INV, acc[mt][nt][1] * HSCALE_INV);
            *reinterpret_cast<float2*>(&Sf[(r + 8) * 388 + col]) =
                make_float2(acc[mt][nt][2] * HSCALE_INV, acc[mt][nt][3] * HSCALE_INV);
        }
    }
    __syncthreads();

    for (int i = tid; i < FROWS * 48; i += 512) {
        int r  = i / 48;
        int c8 = (i - r * 48) * 8;
        const float* Sp = &Sf[r * 388 + c8];
        __half2 h0 = __floats2half2_rn(Sp[0], Sp[1]);
        __half2 h1 = __floats2half2_rn(Sp[2], Sp[3]);
        __half2 h2 = __floats2half2_rn(Sp[4], Sp[5]);
        __half2 h3 = __floats2half2_rn(Sp[6], Sp[7]);
        uint4 pack;
        pack.x = *reinterpret_cast<unsigned int*>(&h0);
        pack.y = *reinterpret_cast<unsigned int*>(&h1);
        pack.z = *reinterpret_cast<unsigned int*>(&h2);
        pack.w = *reinterpret_cast<unsigned int*>(&h3);
        *reinterpret_cast<uint4*>(g_filtP + (size_t)(row0 + r) * DET_U + c8) = pack;
    }
}

// ---------------- kernel 1b: build padded bilinear quads from plain rows ----------------
__global__ __launch_bounds__(256) void requad_kernel() {
    int j = threadIdx.x;
    if (j < 1 || j > 192) return;
    int vp = blockIdx.x;            // 0..256  (= v0+1)
    int a0 = blockIdx.y * 2;        // angles a0, a0+1

    bool rowok = (vp >= 1) && (vp <= 255);
    int c0 = 2 * j;

    #pragma unroll
    for (int k = 0; k < 2; k++) {
        int a = a0 + k;
        uint4 outv = make_uint4(0u, 0u, 0u, 0u);
        if (rowok) {
            const __half* top = g_filtP + ((size_t)a * DET_V + (vp - 1)) * DET_U + (c0 - 2);
            const __half* bot = top + DET_U;
            uint32_t t0 = *reinterpret_cast<const uint32_t*>(top);
            uint32_t b0 = *reinterpret_cast<const uint32_t*>(bot);
            __half2 T0 = *reinterpret_cast<__half2*>(&t0);
            __half2 B0 = *reinterpret_cast<__half2*>(&b0);
            __half2 x  = __lows2half2(T0, B0);
            __half2 y  = __highs2half2(T0, B0);
            outv.x = *reinterpret_cast<unsigned int*>(&x);
            outv.y = *reinterpret_cast<unsigned int*>(&y);
            if (j <= 191) {
                uint32_t t1 = *reinterpret_cast<const uint32_t*>(top + 2);
                uint32_t b1 = *reinterpret_cast<const uint32_t*>(bot + 2);
                __half2 T1 = *reinterpret_cast<__half2*>(&t1);
                __half2 B1 = *reinterpret_cast<__half2*>(&b1);
                __half2 wv = __lows2half2(T1, B1);
                outv.z = outv.y;
                outv.w = *reinterpret_cast<unsigned int*>(&wv);
            }
        }
        size_t qidx = ((size_t)a * QS_ANG + (size_t)(vp + QROW_SHIFT) * QS_U + c0) >> 1;
        g_filtQ4[qidx] = outv;
    }
}

// ---------------- kernel 2: backprojection (exact R13 config: MLP=8, 10 blocks/SM) ----------------
#define ZPT 8
__global__ __launch_bounds__(128, 10) void bp_kernel() {
    __shared__ float2 strig[ACHUNK];
    int tid = threadIdx.x;
    int ach = blockIdx.z;
    int a0  = ach * ACHUNK;
    for (int i = tid; i < ACHUNK; i += 128) strig[i] = g_trig[a0 + i];
    __syncthreads();

    int x  = tid;
    int y  = blockIdx.x;
    int z0 = blockIdx.y * ZPT;

    float xc  = (float)x  - CC;
    float yc  = (float)y  - CC;
    float zc0 = (float)z0 - CC;

    float acc[ZPT];
    #pragma unroll
    for (int j = 0; j < ZPT; j++) acc[j] = 0.f;

    const uint2* Q = reinterpret_cast<const uint2*>(g_filtQ4) + (size_t)a0 * QS_ANG;

    #pragma unroll 2
    for (int ai = 0; ai < ACHUNK; ai++) {
        float2 cs = strig[ai];
        float c = cs.x, s = cs.y;
        float t = yc * c - xc * s;
        float r = D_SO - (xc * c + yc * s);
        float rinv = __fdividef(1.0f, r);

        float iu  = fmaf(D_SD * t, rinv, CU);
        int   u0r = __float2int_rd(iu);
        float fu  = iu - __int2float_rn(u0r);
        int   u0i = min(max(u0r, -1), DET_U - 1);
        __half2 fu2 = __float2half2_rn(fu);

        float wq = D_SO * rinv;
        float w  = wq * wq;

        float kz  = D_SD * rinv;
        float iv0 = fmaf(kz, zc0, CV);

        const uint2* rowp = Q + (size_t)ai * QS_ANG + (30 * QS_U + 2) + u0i;

        // phase A: compute all offsets + issue all loads (MLP=8)
        float fv[ZPT];
        uint2 q[ZPT];
        #pragma unroll
        for (int j = 0; j < ZPT; j++) {
            float iv  = fmaf(kz, (float)j, iv0);
            int   v0r = __float2int_rd(iv);
            fv[j] = iv - __int2float_rn(v0r);
            q[j]  = rowp[v0r * QS_U];
        }

        // phase B: lerp + accumulate
        #pragma unroll
        for (int j = 0; j < ZPT; j++) {
            __half2 A = *reinterpret_cast<__half2*>(&q[j].x);
            __half2 B = *reinterpret_cast<__half2*>(&q[j].y);
            __half2 E = __hfma2(fu2, __hsub2(B, A), A);
            float2 e = __half22float2(E);
            float val = fmaf(fv[j], e.y - e.x, e.x);
            acc[j] = fmaf(val, w, acc[j]);
        }
    }

    float* part = g_part + (size_t)ach * VOL_ELEMS;
    size_t obase = ((size_t)z0 * VOL_N + y) * VOL_N + x;
    #pragma unroll
    for (int j = 0; j < ZPT; j++) {
        part[obase + (size_t)j * VOL_N * VOL_N] = acc[j];
    }
}

// ---------------- kernel 3: sum partials ----------------
__global__ __launch_bounds__(256) void add_kernel(float* __restrict__ out) {
    size_t i = ((size_t)blockIdx.x * 256 + threadIdx.x) * 4;
    float4 o = make_float4(0.f, 0.f, 0.f, 0.f);
    #pragma unroll
    for (int p = 0; p < ASPLIT; p++) {
        float4 v = *reinterpret_cast<const float4*>(g_part + (size_t)p * VOL_ELEMS + i);
        o.x += v.x; o.y += v.y; o.z += v.z; o.w += v.w;
    }
    *reinterpret_cast<float4*>(out + i) = o;
}

// ---------------- launch ----------------
extern "C" void kernel_launch(void* const* d_in, const int* in_sizes, int n_in,
                              void* d_out, int out_size) {
    const float* proj   = nullptr;
    const float* ramp   = nullptr;
    const float* redund = nullptr;
    for (int i = 0; i < n_in; i++) {
        if (in_sizes[i] == DET_U/2 + 1)                    ramp   = (const float*)d_in[i];
        else if (in_sizes[i] == N_ANG * DET_U)             redund = (const float*)d_in[i];
        else if (in_sizes[i] == N_ANG * DET_V * DET_U)     proj   = (const float*)d_in[i];
    }

    cudaFuncSetAttribute(filt_gemm_kernel,
                         cudaFuncAttributeMaxDynamicSharedMemorySize, FILT_SMEM);

    // bp_kernel is launch #4 (the one ncu captures)
    prep_h_kernel<<<DET_U, 192>>>(ramp);                                     // #1
    filt_gemm_kernel<<<(N_ANG*DET_V)/FROWS, 512, FILT_SMEM>>>(proj, redund); // #2
    dim3 qgrid(257, N_ANG/2);
    requad_kernel<<<qgrid, 256>>>();                                         // #3
    dim3 grid(VOL_N, VOL_N / ZPT, ASPLIT);
    bp_kernel<<<grid, 128>>>();                                              // #4 <- profiled
    add_kernel<<<VOL_ELEMS/(256*4), 256>>>((float*)d_out);                   // #5
}

// round 17
// speedup vs baseline: 1.0246x; 1.0246x over previous
#include <cuda_runtime.h>
#include <cuda_fp16.h>
#include <math.h>
#include <stdint.h>

// ---------------- problem constants ----------------
#define N_ANG   256
#define DET_V   256
#define DET_U   384
#define VOL_N   128
#define D_SO    500.0f
#define D_SD    1000.0f
#define CU      191.5f
#define CV      127.5f
#define CC      63.5f
#define VOL_ELEMS (VOL_N*VOL_N*VOL_N)

// exponent re-centering for the fp16 GEMM: h' = h * 2^9 (exact), undone in epilogue
#define HSCALE     512.0f
#define HSCALE_INV (1.0f/512.0f)

// quad buffer geometry (row index = v0 + 30; border rows stay zero: zero-initialized
// __device__ global, never written)
#define QS_U    392
#define QS_ROWS 314
#define QS_ANG  (QS_U*QS_ROWS)
#define QROW_SHIFT 29

// angle split for BP occupancy
#define ASPLIT  8
#define ACHUNK  (N_ANG/ASPLIT)      // 32

// ---------------- device scratch (zero-initialized at module load) ----------------
__device__ float    g_hf[2*DET_U];                        // h (fp32, duplicated)
__device__ uint32_t g_hpdh[2*DET_U];                      // half2 {hi(h'[i]), hi(h'[i-1])}
__device__ uint32_t g_hpdl[2*DET_U];                      // half2 {lo(h'[i]), lo(h'[i-1])}
__device__ float2   g_trig[N_ANG];
__device__ __half   g_filtP[(size_t)N_ANG*DET_V*DET_U];   // filtered proj, plain half rows (50MB)
__device__ uint4    g_filtQ4[(size_t)N_ANG*QS_ANG/2];     // padded bilinear quads (252MB)
__device__ float    g_part[(size_t)ASPLIT*VOL_ELEMS];

// ---------------- kernel 0: h = irfft(ramp)*(pi/N_ANG) (fp64 DFT) + trig table ----------------
__global__ __launch_bounds__(192) void prep_h_kernel(const float* __restrict__ ramp) {
    __shared__ double swarp[6];
    int n = blockIdx.x;
    int k = threadIdx.x;

    double term;
    if (k == 0) {
        double nyq = (double)ramp[DET_U/2] * (((n & 1) == 0) ? 1.0 : -1.0);
        term = (double)ramp[0] + nyq;
    } else {
        int m = (k * n) % DET_U;
        term = 2.0 * (double)ramp[k] * cos(2.0 * M_PI * (double)m / (double)DET_U);
    }
    #pragma unroll
    for (int off = 16; off > 0; off >>= 1)
        term += __shfl_down_sync(0xffffffffu, term, off);
    if ((k & 31) == 0) swarp[k >> 5] = term;
    __syncthreads();
    if (k == 0) {
        double acc = 0.0;
        #pragma unroll
        for (int w = 0; w < 6; w++) acc += swarp[w];
        float h = (float)(acc / (double)DET_U * (M_PI / (double)N_ANG));
        g_hf[n] = h;
        g_hf[n + DET_U] = h;
        if (n < N_ANG) {
            double th = (double)n * (2.0 * M_PI / (double)N_ANG);
            g_trig[n] = make_float2((float)cos(th), (float)sin(th));
        }
    }
}

// ---------------- kernels 0b/0c: descending-pair fp16 hi/lo tables of h' = 512*h ----------------
__global__ __launch_bounds__(768) void prep_pair_hi_kernel() {
    int i  = threadIdx.x;
    int im = (i == 0) ? (2*DET_U - 1) : (i - 1);
    __half2 p = __floats2half2_rn(g_hf[i] * HSCALE, g_hf[im] * HSCALE);
    g_hpdh[i] = *reinterpret_cast<uint32_t*>(&p);
}
__global__ __launch_bounds__(768) void prep_pair_lo_kernel() {
    int i  = threadIdx.x;
    int im = (i == 0) ? (2*DET_U - 1) : (i - 1);
    float h0 = g_hf[i]  * HSCALE;
    float h1 = g_hf[im] * HSCALE;
    float l0 = h0 - __half2float(__float2half_rn(h0));
    float l1 = h1 - __half2float(__float2half_rn(h1));
    __half2 p = __floats2half2_rn(l0, l1);
    g_hpdl[i] = *reinterpret_cast<uint32_t*>(&p);
}

// ---------------- kernel 1: filter as 3-pass FP16 tensor-core GEMM (circulant B) ----------------
// R12-proven layout; MMA emission reordered pass-by-pass so each accumulator's
// dependent MMAs have 5 independent MMAs between them (covers HMMA latency).
#define FROWS 32
#define SH    392
#define FILT_SMEM (2*FROWS*SH*2 + 2*768*4)

#define MMA16(acc, A, b0, b1)                                               \
    asm volatile(                                                           \
        "mma.sync.aligned.m16n8k16.row.col.f32.f16.f16.f32 "                \
        "{%0,%1,%2,%3}, {%4,%5,%6,%7}, {%8,%9}, {%0,%1,%2,%3};"             \
        : "+f"((acc)[0]), "+f"((acc)[1]), "+f"((acc)[2]), "+f"((acc)[3])    \
        : "r"((A)[0]), "r"((A)[1]), "r"((A)[2]), "r"((A)[3]),               \
          "r"(b0), "r"(b1));

__global__ __launch_bounds__(512, 2) void filt_gemm_kernel(const float* __restrict__ proj,
                                                           const float* __restrict__ redund) {
    extern __shared__ __half smh[];
    __half*   sHi  = smh;
    __half*   sLo  = smh + FROWS*SH;
    uint32_t* sTbH = reinterpret_cast<uint32_t*>(smh + 2*FROWS*SH);
    uint32_t* sTbL = sTbH + 768;

    int tid  = threadIdx.x;
    int b    = blockIdx.x;
    int a    = b >> 3;
    int v0   = (b & 7) << 5;
    int row0 = b << 5;

    const float* prow = proj   + (size_t)row0 * DET_U;
    const float* rrow = redund + (size_t)a    * DET_U;

    for (int i = tid; i < FROWS * DET_U; i += 512) {
        int r = i / DET_U;
        int c = i - r * DET_U;
        float vv = (float)(v0 + r) - CV;
        float uu = (float)c - CU;
        float cw = D_SD * rsqrtf(D_SD*D_SD + vv*vv + uu*uu);
        float val = prow[i] * cw * rrow[c];
        __half hi = __float2half_rn(val);
        __half lo = __float2half_rn(val - __half2float(hi));
        sHi[r * SH + c] = hi;
        sLo[r * SH + c] = lo;
    }
    for (int i = tid; i < 768; i += 512) {
        sTbH[i] = g_hpdh[i];
        sTbL[i] = g_hpdl[i];
    }
    __syncthreads();

    int w    = tid >> 5;
    int lane = tid & 31;
    int gr   = lane >> 2;
    int tig  = lane & 3;
    int n0   = w * 24;

    float acc[2][3][4];
    #pragma unroll
    for (int mt = 0; mt < 2; mt++)
        #pragma unroll
        for (int nt = 0; nt < 3; nt++)
            #pragma unroll
            for (int q = 0; q < 4; q++) acc[mt][nt][q] = 0.f;

    int arow = gr * SH + 2 * tig;
    int bC   = n0 + gr - 2 * tig + 384;

    #pragma unroll 4
    for (int ksg = 0; ksg < 24; ksg++) {
        int ks16 = ksg * 16;
        uint32_t Ah[2][4], Al[2][4];
        #pragma unroll
        for (int mt = 0; mt < 2; mt++) {
            int base = arow + mt * (16 * SH) + ks16;
            Ah[mt][0] = *reinterpret_cast<const uint32_t*>(&sHi[base]);
            Ah[mt][1] = *reinterpret_cast<const uint32_t*>(&sHi[base + 8*SH]);
            Ah[mt][2] = *reinterpret_cast<const uint32_t*>(&sHi[base + 8]);
            Ah[mt][3] = *reinterpret_cast<const uint32_t*>(&sHi[base + 8*SH + 8]);
            Al[mt][0] = *reinterpret_cast<const uint32_t*>(&sLo[base]);
            Al[mt][1] = *reinterpret_cast<const uint32_t*>(&sLo[base + 8*SH]);
            Al[mt][2] = *reinterpret_cast<const uint32_t*>(&sLo[base + 8]);
            Al[mt][3] = *reinterpret_cast<const uint32_t*>(&sLo[base + 8*SH + 8]);
        }
        uint32_t b0h[3], b1h[3], b0l[3], b1l[3];
        #pragma unroll
        for (int nt = 0; nt < 3; nt++) {
            int i0 = bC + nt * 8 - ks16;
            b0h[nt] = sTbH[i0];
            b1h[nt] = sTbH[i0 - 8];
            b0l[nt] = sTbL[i0];
            b1l[nt] = sTbL[i0 - 8];
        }
        // pass 1: hi*hi for all 6 accumulators (independent)
        #pragma unroll
        for (int nt = 0; nt < 3; nt++)
            #pragma unroll
            for (int mt = 0; mt < 2; mt++)
                MMA16(acc[mt][nt], Ah[mt], b0h[nt], b1h[nt]);
        // pass 2: hi*lo
        #pragma unroll
        for (int nt = 0; nt < 3; nt++)
            #pragma unroll
            for (int mt = 0; mt < 2; mt++)
                MMA16(acc[mt][nt], Ah[mt], b0l[nt], b1l[nt]);
        // pass 3: lo*hi
        #pragma unroll
        for (int nt = 0; nt < 3; nt++)
            #pragma unroll
            for (int mt = 0; mt < 2; mt++)
                MMA16(acc[mt][nt], Al[mt], b0h[nt], b1h[nt]);
    }

    __syncthreads();
    float* Sf = reinterpret_cast<float*>(smh);
    #pragma unroll
    for (int mt = 0; mt < 2; mt++) {
        int r = 16 * mt + gr;
        #pragma unroll
        for (int nt = 0; nt < 3; nt++) {
            int col = n0 + nt * 8 + 2 * tig;
            *reinterpret_cast<float2*>(&Sf[r * 388 + col]) =
                make_float2(acc[mt][nt][0] * HSCALE_INV, acc[mt][nt][1] * HSCALE_INV);
            *reinterpret_cast<float2*>(&Sf[(r + 8) * 388 + col]) =
                make_float2(acc[mt][nt][2] * HSCALE_INV, acc[mt][nt][3] * HSCALE_INV);
        }
    }
    __syncthreads();

    for (int i = tid; i < FROWS * 48; i += 512) {
        int r  = i / 48;
        int c8 = (i - r * 48) * 8;
        const float* Sp = &Sf[r * 388 + c8];
        __half2 h0 = __floats2half2_rn(Sp[0], Sp[1]);
        __half2 h1 = __floats2half2_rn(Sp[2], Sp[3]);
        __half2 h2 = __floats2half2_rn(Sp[4], Sp[5]);
        __half2 h3 = __floats2half2_rn(Sp[6], Sp[7]);
        uint4 pack;
        pack.x = *reinterpret_cast<unsigned int*>(&h0);
        pack.y = *reinterpret_cast<unsigned int*>(&h1);
        pack.z = *reinterpret_cast<unsigned int*>(&h2);
        pack.w = *reinterpret_cast<unsigned int*>(&h3);
        *reinterpret_cast<uint4*>(g_filtP + (size_t)(row0 + r) * DET_U + c8) = pack;
    }
}

// ---------------- kernel 1b: build padded bilinear quads from plain rows ----------------
__global__ __launch_bounds__(256) void requad_kernel() {
    int j = threadIdx.x;
    if (j < 1 || j > 192) return;
    int vp = blockIdx.x;            // 0..256  (= v0+1)
    int a0 = blockIdx.y * 2;        // angles a0, a0+1

    bool rowok = (vp >= 1) && (vp <= 255);
    int c0 = 2 * j;

    #pragma unroll
    for (int k = 0; k < 2; k++) {
        int a = a0 + k;
        uint4 outv = make_uint4(0u, 0u, 0u, 0u);
        if (rowok) {
            const __half* top = g_filtP + ((size_t)a * DET_V + (vp - 1)) * DET_U + (c0 - 2);
            const __half* bot = top + DET_U;
            uint32_t t0 = *reinterpret_cast<const uint32_t*>(top);
            uint32_t b0 = *reinterpret_cast<const uint32_t*>(bot);
            __half2 T0 = *reinterpret_cast<__half2*>(&t0);
            __half2 B0 = *reinterpret_cast<__half2*>(&b0);
            __half2 x  = __lows2half2(T0, B0);
            __half2 y  = __highs2half2(T0, B0);
            outv.x = *reinterpret_cast<unsigned int*>(&x);
            outv.y = *reinterpret_cast<unsigned int*>(&y);
            if (j <= 191) {
                uint32_t t1 = *reinterpret_cast<const uint32_t*>(top + 2);
                uint32_t b1 = *reinterpret_cast<const uint32_t*>(bot + 2);
                __half2 T1 = *reinterpret_cast<__half2*>(&t1);
                __half2 B1 = *reinterpret_cast<__half2*>(&b1);
                __half2 wv = __lows2half2(T1, B1);
                outv.z = outv.y;
                outv.w = *reinterpret_cast<unsigned int*>(&wv);
            }
        }
        size_t qidx = ((size_t)a * QS_ANG + (size_t)(vp + QROW_SHIFT) * QS_U + c0) >> 1;
        g_filtQ4[qidx] = outv;
    }
}

// ---------------- kernel 2: backprojection (exact R13 config: MLP=8, 10 blocks/SM) ----------------
#define ZPT 8
__global__ __launch_bounds__(128, 10) void bp_kernel() {
    __shared__ float2 strig[ACHUNK];
    int tid = threadIdx.x;
    int ach = blockIdx.z;
    int a0  = ach * ACHUNK;
    for (int i = tid; i < ACHUNK; i += 128) strig[i] = g_trig[a0 + i];
    __syncthreads();

    int x  = tid;
    int y  = blockIdx.x;
    int z0 = blockIdx.y * ZPT;

    float xc  = (float)x  - CC;
    float yc  = (float)y  - CC;
    float zc0 = (float)z0 - CC;

    float acc[ZPT];
    #pragma unroll
    for (int j = 0; j < ZPT; j++) acc[j] = 0.f;

    const uint2* Q = reinterpret_cast<const uint2*>(g_filtQ4) + (size_t)a0 * QS_ANG;

    #pragma unroll 2
    for (int ai = 0; ai < ACHUNK; ai++) {
        float2 cs = strig[ai];
        float c = cs.x, s = cs.y;
        float t = yc * c - xc * s;
        float r = D_SO - (xc * c + yc * s);
        float rinv = __fdividef(1.0f, r);

        float iu  = fmaf(D_SD * t, rinv, CU);
        int   u0r = __float2int_rd(iu);
        float fu  = iu - __int2float_rn(u0r);
        int   u0i = min(max(u0r, -1), DET_U - 1);
        __half2 fu2 = __float2half2_rn(fu);

        float wq = D_SO * rinv;
        float w  = wq * wq;

        float kz  = D_SD * rinv;
        float iv0 = fmaf(kz, zc0, CV);

        const uint2* rowp = Q + (size_t)ai * QS_ANG + (30 * QS_U + 2) + u0i;

        // phase A: compute all offsets + issue all loads (MLP=8)
        float fv[ZPT];
        uint2 q[ZPT];
        #pragma unroll
        for (int j = 0; j < ZPT; j++) {
            float iv  = fmaf(kz, (float)j, iv0);
            int   v0r = __float2int_rd(iv);
            fv[j] = iv - __int2float_rn(v0r);
            q[j]  = rowp[v0r * QS_U];
        }

        // phase B: lerp + accumulate
        #pragma unroll
        for (int j = 0; j < ZPT; j++) {
            __half2 A = *reinterpret_cast<__half2*>(&q[j].x);
            __half2 B = *reinterpret_cast<__half2*>(&q[j].y);
            __half2 E = __hfma2(fu2, __hsub2(B, A), A);
            float2 e = __half22float2(E);
            float val = fmaf(fv[j], e.y - e.x, e.x);
            acc[j] = fmaf(val, w, acc[j]);
        }
    }

    float* part = g_part + (size_t)ach * VOL_ELEMS;
    size_t obase = ((size_t)z0 * VOL_N + y) * VOL_N + x;
    #pragma unroll
    for (int j = 0; j < ZPT; j++) {
        part[obase + (size_t)j * VOL_N * VOL_N] = acc[j];
    }
}

// ---------------- kernel 3: sum partials ----------------
__global__ __launch_bounds__(256) void add_kernel(float* __restrict__ out) {
    size_t i = ((size_t)blockIdx.x * 256 + threadIdx.x) * 4;
    float4 o = make_float4(0.f, 0.f, 0.f, 0.f);
    #pragma unroll
    for (int p = 0; p < ASPLIT; p++) {
        float4 v = *reinterpret_cast<const float4*>(g_part + (size_t)p * VOL_ELEMS + i);
        o.x += v.x; o.y += v.y; o.z += v.z; o.w += v.w;
    }
    *reinterpret_cast<float4*>(out + i) = o;
}

// ---------------- launch ----------------
extern "C" void kernel_launch(void* const* d_in, const int* in_sizes, int n_in,
                              void* d_out, int out_size) {
    const float* proj   = nullptr;
    const float* ramp   = nullptr;
    const float* redund = nullptr;
    for (int i = 0; i < n_in; i++) {
        if (in_sizes[i] == DET_U/2 + 1)                    ramp   = (const float*)d_in[i];
        else if (in_sizes[i] == N_ANG * DET_U)             redund = (const float*)d_in[i];
        else if (in_sizes[i] == N_ANG * DET_V * DET_U)     proj   = (const float*)d_in[i];
    }

    cudaFuncSetAttribute(filt_gemm_kernel,
                         cudaFuncAttributeMaxDynamicSharedMemorySize, FILT_SMEM);

    // filt_gemm is launch #4 (the one ncu captures)
    prep_h_kernel<<<DET_U, 192>>>(ramp);                                     // #1
    prep_pair_hi_kernel<<<1, 768>>>();                                       // #2
    prep_pair_lo_kernel<<<1, 768>>>();                                       // #3
    filt_gemm_kernel<<<(N_ANG*DET_V)/FROWS, 512, FILT_SMEM>>>(proj, redund); // #4 <- profiled
    dim3 qgrid(257, N_ANG/2);
    requad_kernel<<<qgrid, 256>>>();                                         // #5
    dim3 grid(VOL_N, VOL_N / ZPT, ASPLIT);
    bp_kernel<<<grid, 128>>>();                                              // #6
    add_kernel<<<VOL_ELEMS/(256*4), 256>>>((float*)d_out);                   // #7
}